// round 14
// baseline (speedup 1.0000x reference)
#include <cuda_runtime.h>
#include <cuda_fp16.h>
#include <math.h>
#include <stdint.h>

#define N_NODES 100000
#define F_IN    500
#define F_HID   256
#define F_OUT   40
#define N_EDGES 1600000
#define K_ITERS 10

constexpr float LAMBDA_AMP = 0.5f;
constexpr float GAMMA_ = 1.0f / (2.0f * (1.0f - LAMBDA_AMP));   // 1.0
constexpr float COEF   = GAMMA_ * 2.0f * (1.0f - LAMBDA_AMP);   // 1.0
constexpr float LAM    = GAMMA_ * LAMBDA_AMP;                   // 0.5

// ---------------- device scratch (no allocations allowed) ----------------
__device__ __align__(16) float g_part_h[(size_t)2 * N_NODES * F_OUT];
__device__ __align__(16) float g_h [(size_t)N_NODES * F_OUT];
__device__ __align__(16) __half g_hxa[(size_t)N_NODES * F_OUT]; // fp16 ping
__device__ __align__(16) __half g_hxb[(size_t)N_NODES * F_OUT]; // fp16 pong (also fp16 h copy)
__device__ int    g_count[N_NODES];
__device__ int    g_rowstart[N_NODES];
__device__ int    g_cursor[N_NODES];
__device__ float  g_dinv[N_NODES];
__device__ __align__(16) float2 g_csr_sw[N_EDGES];   // {src_bits, weight}
__device__ int    g_part[512];
__device__ int    g_pscan[512];

// ---------------- setup kernels ----------------
__global__ void zero_kernel() {
    int i = blockIdx.x * blockDim.x + threadIdx.x;
    if (i < N_NODES) { g_count[i] = 0; g_cursor[i] = 0; }
}

__global__ void hist_kernel(const int* __restrict__ dst) {
    for (int e = blockIdx.x * blockDim.x + threadIdx.x; e < N_EDGES;
         e += gridDim.x * blockDim.x)
        atomicAdd(&g_count[dst[e]], 1);
}

__global__ void dinv_kernel() {
    int i = blockIdx.x * blockDim.x + threadIdx.x;
    if (i < N_NODES) {
        float deg = (float)(g_count[i] + 1);
        g_dinv[i] = rsqrtf(deg);
    }
}

__global__ void scan_block(const int* __restrict__ in, int* __restrict__ out,
                           int* __restrict__ partials, int n) {
    int t = threadIdx.x, lane = t & 31, w = t >> 5;
    int g = blockIdx.x * 512 + 2 * t;
    int v0 = (g     < n) ? in[g]     : 0;
    int v1 = (g + 1 < n) ? in[g + 1] : 0;
    int s = v0 + v1;
    int x = s;
#pragma unroll
    for (int o = 1; o < 32; o <<= 1) {
        int y = __shfl_up_sync(0xffffffffu, x, o);
        if (lane >= o) x += y;
    }
    __shared__ int wsum[8];
    if (lane == 31) wsum[w] = x;
    __syncthreads();
    if (w == 0) {
        int ws = (lane < 8) ? wsum[lane] : 0;
#pragma unroll
        for (int o = 1; o < 8; o <<= 1) {
            int y = __shfl_up_sync(0xffffffffu, ws, o);
            if (lane >= o) ws += y;
        }
        if (lane < 8) wsum[lane] = ws;
    }
    __syncthreads();
    int base = (w > 0) ? wsum[w - 1] : 0;
    int excl = base + x - s;
    if (g     < n) out[g]     = excl;
    if (g + 1 < n) out[g + 1] = excl + v0;
    if (t == 255) partials[blockIdx.x] = base + x;
}

__global__ void add_offsets(int* __restrict__ out, const int* __restrict__ pscan, int n) {
    int i = blockIdx.x * blockDim.x + threadIdx.x;
    if (i < n) out[i] += pscan[i >> 9];
}

__global__ void scatter_kernel(const int* __restrict__ src, const int* __restrict__ dst) {
    for (int e = blockIdx.x * blockDim.x + threadIdx.x; e < N_EDGES;
         e += gridDim.x * blockDim.x) {
        int d = dst[e], s = src[e];
        int pos = g_rowstart[d] + atomicAdd(&g_cursor[d], 1);
        g_csr_sw[pos] = make_float2(__int_as_float(s), g_dinv[s] * g_dinv[d]);
    }
}

// ---------------- fused MLP (tf32 mma.sync), big tiles + 3-stage cp.async ----
// A-fragments via ldmatrix.m8n8.x4.b16 (tf32 layout maps exactly)
#define BM 256
#define BN 128
#define BK 32
#define AS_STRIDE 36
#define BS_STRIDE 136
#define HT_STRIDE 136
#define W2_STRIDE 136
#define AS_W 9216
#define BS_W 4352
#define B_BASE 27648
#define DSMEM_BYTES (40704 * 4)

__device__ __forceinline__ uint32_t smem_u32(const void* p) {
    uint32_t a;
    asm("{ .reg .u64 t; cvta.to.shared.u64 t, %1; cvt.u32.u64 %0, t; }"
        : "=r"(a) : "l"(p));
    return a;
}
__device__ __forceinline__ void cp16(uint32_t dst, const void* src, int srcsz) {
    asm volatile("cp.async.ca.shared.global [%0], [%1], 16, %2;"
                 :: "r"(dst), "l"(src), "r"(srcsz) : "memory");
}
#define CP_COMMIT() asm volatile("cp.async.commit_group;" ::: "memory")
#define CP_WAIT2()  asm volatile("cp.async.wait_group 2;" ::: "memory")
#define CP_WAIT1()  asm volatile("cp.async.wait_group 1;" ::: "memory")
#define CP_WAIT0()  asm volatile("cp.async.wait_group 0;" ::: "memory")

__device__ __forceinline__ uint32_t f2tf32(float f) {
    uint32_t r;
    asm("cvt.rna.tf32.f32 %0, %1;" : "=r"(r) : "f"(f));
    return r;
}

__global__ __launch_bounds__(256, 1) void gemm1_mma_kernel(const float* __restrict__ A,
                                                           const float* __restrict__ B,
                                                           const float* __restrict__ bias,
                                                           const float* __restrict__ W2) {
    extern __shared__ __align__(16) uint32_t smem_u[];

    int bm = blockIdx.y * BM, bn = blockIdx.x * BN;
    int tid = threadIdx.x;
    int warpId = tid >> 5, lane = tid & 31;
    int warpM = warpId & 3;
    int warpN = warpId >> 2;
    int group = lane >> 2;
    int tig   = lane & 3;

    uint32_t sbase = smem_u32(smem_u);

    // ldmatrix per-lane A address components:
    // row = warpM*64 + (lane&15) (+ mi*16), col word = (lane&16 ? 4 : 0) (+ kb)
    int lm_row  = warpM * 64 + (lane & 15);
    int lm_kcol = (lane & 16) ? 4 : 0;

    float acc[4][8][4] = {};

    auto issue_stage = [&](int it) {
        int buf = it % 3;
        int k0 = it * BK;
        uint32_t as_addr = sbase + (buf * AS_W) * 4;
        uint32_t bs_addr = sbase + (B_BASE + buf * BS_W) * 4;
#pragma unroll
        for (int i = 0; i < 8; i++) {
            int idx = tid + i * 256;
            int r = idx >> 3, q = idx & 7;
            int gm = bm + r, gk = k0 + q * 4;
            bool ok = (gm < N_NODES) && (gk < F_IN);
            int gmc = ok ? gm : 0, gkc = ok ? gk : 0;
            cp16(as_addr + (r * AS_STRIDE + q * 4) * 4,
                 A + (size_t)gmc * F_IN + gkc, ok ? 16 : 0);
        }
#pragma unroll
        for (int i = 0; i < 4; i++) {
            int idx = tid + i * 256;
            int kk = idx >> 5, c4 = idx & 31;
            int gk = k0 + kk;
            bool ok = (gk < F_IN);
            int gkc = ok ? gk : 0;
            cp16(bs_addr + (kk * BS_STRIDE + c4 * 4) * 4,
                 B + (size_t)gkc * F_HID + bn + c4 * 4, ok ? 16 : 0);
        }
        CP_COMMIT();
    };

    issue_stage(0);
    issue_stage(1);
    for (int it = 0; it < 16; it++) {
        int buf = it % 3;
        if (it <= 13) { issue_stage(it + 2); CP_WAIT2(); }
        else if (it == 14) { CP_WAIT1(); }
        else { CP_WAIT0(); }
        __syncthreads();

        const uint32_t* Bs = smem_u + B_BASE + buf * BS_W;
        uint32_t a_lm = sbase + (buf * AS_W) * 4
                      + (lm_row * AS_STRIDE + lm_kcol) * 4;
#pragma unroll
        for (int ks = 0; ks < BK / 8; ks++) {
            int kb = ks * 8;
            uint32_t af[4][4];
#pragma unroll
            for (int mi = 0; mi < 4; mi++) {
                uint32_t addr = a_lm + (mi * 16 * AS_STRIDE + kb) * 4;
                asm volatile(
                    "ldmatrix.sync.aligned.m8n8.x4.shared.b16 {%0,%1,%2,%3}, [%4];"
                    : "=r"(af[mi][0]), "=r"(af[mi][1]),
                      "=r"(af[mi][2]), "=r"(af[mi][3])
                    : "r"(addr));
            }
            uint32_t bf[8][2];
#pragma unroll
            for (int ni = 0; ni < 8; ni++) {
                int c0 = warpN * 64 + ni * 8 + group;
                bf[ni][0] = Bs[(kb + tig) * BS_STRIDE + c0];
                bf[ni][1] = Bs[(kb + tig + 4) * BS_STRIDE + c0];
            }
#pragma unroll
            for (int mi = 0; mi < 4; mi++)
#pragma unroll
                for (int ni = 0; ni < 8; ni++) {
                    asm volatile(
                        "mma.sync.aligned.m16n8k8.row.col.f32.tf32.tf32.f32 "
                        "{%0,%1,%2,%3}, {%4,%5,%6,%7}, {%8,%9}, {%0,%1,%2,%3};"
                        : "+f"(acc[mi][ni][0]), "+f"(acc[mi][ni][1]),
                          "+f"(acc[mi][ni][2]), "+f"(acc[mi][ni][3])
                        : "r"(af[mi][0]), "r"(af[mi][1]), "r"(af[mi][2]), "r"(af[mi][3]),
                          "r"(bf[ni][0]), "r"(bf[ni][1]));
                }
        }
        __syncthreads();
    }

    uint32_t* Ht  = smem_u;
    uint32_t* W2s = smem_u + 34816;

#pragma unroll
    for (int mi = 0; mi < 4; mi++) {
#pragma unroll
        for (int ni = 0; ni < 8; ni++) {
            int lc = warpN * 64 + ni * 8 + tig * 2;
            float bz0 = bias[bn + lc], bz1 = bias[bn + lc + 1];
            int r0 = warpM * 64 + mi * 16 + group;
            Ht[r0 * HT_STRIDE + lc]     = f2tf32(fmaxf(acc[mi][ni][0] + bz0, 0.f));
            Ht[r0 * HT_STRIDE + lc + 1] = f2tf32(fmaxf(acc[mi][ni][1] + bz1, 0.f));
            int r1 = r0 + 8;
            Ht[r1 * HT_STRIDE + lc]     = f2tf32(fmaxf(acc[mi][ni][2] + bz0, 0.f));
            Ht[r1 * HT_STRIDE + lc + 1] = f2tf32(fmaxf(acc[mi][ni][3] + bz1, 0.f));
        }
    }
    for (int idx = tid; idx < 40 * 128; idx += 256) {
        int n = idx >> 7, kk = idx & 127;
        W2s[n * W2_STRIDE + kk] = f2tf32(W2[(size_t)(bn + kk) * F_OUT + n]);
    }
    __syncthreads();

    float acc2[2][5][4] = {};
    int wrow = warpId * 32;
#pragma unroll
    for (int ks = 0; ks < 16; ks++) {
        int kb = ks * 8;
        uint32_t af[2][4];
#pragma unroll
        for (int mi = 0; mi < 2; mi++) {
            int r0 = wrow + mi * 16 + group;
            af[mi][0] = Ht[r0 * HT_STRIDE + kb + tig];
            af[mi][1] = Ht[(r0 + 8) * HT_STRIDE + kb + tig];
            af[mi][2] = Ht[r0 * HT_STRIDE + kb + tig + 4];
            af[mi][3] = Ht[(r0 + 8) * HT_STRIDE + kb + tig + 4];
        }
#pragma unroll
        for (int ni = 0; ni < 5; ni++) {
            uint32_t b0 = W2s[(ni * 8 + group) * W2_STRIDE + kb + tig];
            uint32_t b1 = W2s[(ni * 8 + group) * W2_STRIDE + kb + tig + 4];
#pragma unroll
            for (int mi = 0; mi < 2; mi++) {
                asm volatile(
                    "mma.sync.aligned.m16n8k8.row.col.f32.tf32.tf32.f32 "
                    "{%0,%1,%2,%3}, {%4,%5,%6,%7}, {%8,%9}, {%0,%1,%2,%3};"
                    : "+f"(acc2[mi][ni][0]), "+f"(acc2[mi][ni][1]),
                      "+f"(acc2[mi][ni][2]), "+f"(acc2[mi][ni][3])
                    : "r"(af[mi][0]), "r"(af[mi][1]), "r"(af[mi][2]), "r"(af[mi][3]),
                      "r"(b0), "r"(b1));
            }
        }
    }

    float* part = g_part_h + (size_t)blockIdx.x * N_NODES * F_OUT;
#pragma unroll
    for (int mi = 0; mi < 2; mi++) {
#pragma unroll
        for (int ni = 0; ni < 5; ni++) {
            int col = ni * 8 + tig * 2;
            int r0 = bm + wrow + mi * 16 + group;
            if (r0 < N_NODES)
                *(float2*)(part + (size_t)r0 * F_OUT + col) =
                    make_float2(acc2[mi][ni][0], acc2[mi][ni][1]);
            int r1 = r0 + 8;
            if (r1 < N_NODES)
                *(float2*)(part + (size_t)r1 * F_OUT + col) =
                    make_float2(acc2[mi][ni][2], acc2[mi][ni][3]);
        }
    }
}

// ---------------- fp16 pack/unpack ----------------
__device__ __forceinline__ float4 h4f4(uint2 u) {
    __half2 a = *(__half2*)&u.x, b = *(__half2*)&u.y;
    float2 fa = __half22float2(a), fb = __half22float2(b);
    return make_float4(fa.x, fa.y, fb.x, fb.y);
}
__device__ __forceinline__ uint2 f4h4(float4 v) {
    __half2 a = __floats2half2_rn(v.x, v.y);
    __half2 b = __floats2half2_rn(v.z, v.w);
    uint2 u;
    u.x = *(uint32_t*)&a;
    u.y = *(uint32_t*)&b;
    return u;
}

// ---------------- combine: h = b2 + sum of 2 partials (+ fp16 copy) --------
__global__ __launch_bounds__(256) void combine_kernel(const float* __restrict__ b2) {
    int idx = blockIdx.x * 256 + threadIdx.x;
    const int TOT = N_NODES * F_OUT / 4;
    if (idx >= TOT) return;
    const float4* p = (const float4*)g_part_h;
    const size_t STRIDE4 = (size_t)N_NODES * F_OUT / 4;
    float4 a = p[idx];
    float4 b = p[idx + STRIDE4];
    float4 bz = ((const float4*)b2)[idx % (F_OUT / 4)];
    float4 r;
    r.x = a.x + b.x + bz.x;
    r.y = a.y + b.y + bz.y;
    r.z = a.z + b.z + bz.z;
    r.w = a.w + b.w + bz.w;
    ((float4*)g_h)[idx] = r;
    ((uint2*)g_hxb)[idx] = f4h4(r);    // fp16 copy for iter-0 gathers
}

// ---------------- AMP: warp per node, 3 groups of 10 lanes ----------------
// FINAL: fuse log_softmax + score output (no fp32 xk round trip)
template<bool FINAL>
__global__ __launch_bounds__(256, 5) void amp_kernel(const uint2* __restrict__ xk2,
                                                     __half* __restrict__ xout_h,
                                                     float* __restrict__ lsm,
                                                     float* __restrict__ sout) {
    int node = (blockIdx.x * 256 + threadIdx.x) >> 5;
    int lane = threadIdx.x & 31;
    if (node >= N_NODES) return;
    int g = lane >= 30 ? 3 : (lane >= 20 ? 2 : (lane >= 10 ? 1 : 0));
    int sub = lane - g * 10;
    if (g == 3) sub = lane - 30;
    bool act = lane < 30;

    float4 xq = make_float4(0.f, 0.f, 0.f, 0.f);
    float4 accA = make_float4(0.f, 0.f, 0.f, 0.f);
    float4 accB = make_float4(0.f, 0.f, 0.f, 0.f);
    if (g == 0) {
        xq = h4f4(xk2[(size_t)node * 10 + sub]);
        float dv = g_dinv[node];
        float wself = dv * dv;
        accA.x = wself * xq.x; accA.y = wself * xq.y;
        accA.z = wself * xq.z; accA.w = wself * xq.w;
    }

    int beg = g_rowstart[node];
    int cnt = g_count[node];
    int base = 0;
    for (; base + 6 <= cnt; base += 6) {
        float2 swA = act ? g_csr_sw[beg + base + g]     : make_float2(0.f, 0.f);
        float2 swB = act ? g_csr_sw[beg + base + 3 + g] : make_float2(0.f, 0.f);
        int sA = act ? __float_as_int(swA.x) : 0;
        int sB = act ? __float_as_int(swB.x) : 0;
        float4 xA = h4f4(xk2[(size_t)sA * 10 + sub]);
        float4 xB = h4f4(xk2[(size_t)sB * 10 + sub]);
        accA.x += swA.y * xA.x; accA.y += swA.y * xA.y;
        accA.z += swA.y * xA.z; accA.w += swA.y * xA.w;
        accB.x += swB.y * xB.x; accB.y += swB.y * xB.y;
        accB.z += swB.y * xB.z; accB.w += swB.y * xB.w;
    }
    for (; base < cnt; base += 3) {
        int idx = base + g;
        bool v = act && (idx < cnt);
        float2 sw = v ? g_csr_sw[beg + idx] : make_float2(0.f, 0.f);
        int s = v ? __float_as_int(sw.x) : 0;
        float4 xs = h4f4(xk2[(size_t)s * 10 + sub]);
        accA.x += sw.y * xs.x; accA.y += sw.y * xs.y;
        accA.z += sw.y * xs.z; accA.w += sw.y * xs.w;
    }
    accA.x += accB.x; accA.y += accB.y; accA.z += accB.z; accA.w += accB.w;

    {
        float t1, t2;
        t1 = __shfl_down_sync(0xffffffffu, accA.x, 10);
        t2 = __shfl_down_sync(0xffffffffu, accA.x, 20);
        accA.x += t1 + t2;
        t1 = __shfl_down_sync(0xffffffffu, accA.y, 10);
        t2 = __shfl_down_sync(0xffffffffu, accA.y, 20);
        accA.y += t1 + t2;
        t1 = __shfl_down_sync(0xffffffffu, accA.z, 10);
        t2 = __shfl_down_sync(0xffffffffu, accA.z, 20);
        accA.z += t1 + t2;
        t1 = __shfl_down_sync(0xffffffffu, accA.w, 10);
        t2 = __shfl_down_sync(0xffffffffu, accA.w, 20);
        accA.w += t1 + t2;
    }

    float4 hq = make_float4(0.f, 0.f, 0.f, 0.f);
    float4 d = make_float4(0.f, 0.f, 0.f, 0.f);
    float ss = 0.f;
    if (g == 0) {
        hq = ((const float4*)g_h)[(size_t)node * 10 + sub];
        float4 y;
        y.x = xq.x - COEF * (xq.x - accA.x);
        y.y = xq.y - COEF * (xq.y - accA.y);
        y.z = xq.z - COEF * (xq.z - accA.z);
        y.w = xq.w - COEF * (xq.w - accA.w);
        d.x = y.x - hq.x; d.y = y.y - hq.y; d.z = y.z - hq.z; d.w = y.w - hq.w;
        ss = d.x * d.x + d.y * d.y + d.z * d.z + d.w * d.w;
    }
#pragma unroll
    for (int o = 16; o > 0; o >>= 1) ss += __shfl_xor_sync(0xffffffffu, ss, o);
    float rn = sqrtf(ss);
    float score = (rn > 0.f) ? fmaxf(rn - LAM, 0.f) / rn : 0.f;

    float4 r = make_float4(0.f, 0.f, 0.f, 0.f);
    if (g == 0) {
        r.x = hq.x + score * d.x; r.y = hq.y + score * d.y;
        r.z = hq.z + score * d.z; r.w = hq.w + score * d.w;
    }

    if (!FINAL) {
        if (g == 0)
            ((uint2*)xout_h)[(size_t)node * 10 + sub] = f4h4(r);
    } else {
        // fused log_softmax over the 40 values held by lanes 0-9
        float m_l = -INFINITY, e_l = 0.f;
        if (g == 0)
            m_l = fmaxf(fmaxf(r.x, r.y), fmaxf(r.z, r.w));
#pragma unroll
        for (int o = 16; o > 0; o >>= 1)
            m_l = fmaxf(m_l, __shfl_xor_sync(0xffffffffu, m_l, o));
        if (g == 0)
            e_l = expf(r.x - m_l) + expf(r.y - m_l) + expf(r.z - m_l) + expf(r.w - m_l);
#pragma unroll
        for (int o = 16; o > 0; o >>= 1)
            e_l += __shfl_xor_sync(0xffffffffu, e_l, o);
        float lse = m_l + logf(e_l);
        if (g == 0 && lsm) {
            float4 o4 = make_float4(r.x - lse, r.y - lse, r.z - lse, r.w - lse);
            ((float4*)lsm)[(size_t)node * 10 + sub] = o4;
        }
        if (lane == 0 && sout) sout[node] = score;
    }
}

// ---------------- launch ----------------
extern "C" void kernel_launch(void* const* d_in, const int* in_sizes, int n_in,
                              void* d_out, int out_size) {
    const float* x   = (const float*)d_in[0];
    const float* W1  = (const float*)d_in[1];
    const float* b1  = (const float*)d_in[2];
    const float* W2  = (const float*)d_in[3];
    const float* b2  = (const float*)d_in[4];
    const int* esrc  = (const int*)d_in[5];
    const int* edst  = (const int*)d_in[6];
    float* out = (float*)d_out;

    __half *phxa, *phxb;
    int *pcount, *prowstart, *ppart, *ppscan;
    cudaGetSymbolAddress((void**)&phxa, g_hxa);
    cudaGetSymbolAddress((void**)&phxb, g_hxb);
    cudaGetSymbolAddress((void**)&pcount,    g_count);
    cudaGetSymbolAddress((void**)&prowstart, g_rowstart);
    cudaGetSymbolAddress((void**)&ppart,     g_part);
    cudaGetSymbolAddress((void**)&ppscan,    g_pscan);

    static cudaStream_t s1 = nullptr;
    static cudaEvent_t evFork = nullptr, evJoin = nullptr;
    if (!s1) {
        cudaStreamCreateWithFlags(&s1, cudaStreamNonBlocking);
        cudaEventCreateWithFlags(&evFork, cudaEventDisableTiming);
        cudaEventCreateWithFlags(&evJoin, cudaEventDisableTiming);
        cudaFuncSetAttribute(gemm1_mma_kernel,
                             cudaFuncAttributeMaxDynamicSharedMemorySize, DSMEM_BYTES);
    }

    const int NB = (N_NODES + 255) / 256;

    // fork: setup chain on s1, MLP on main stream
    cudaEventRecord(evFork, 0);
    cudaStreamWaitEvent(s1, evFork, 0);

    zero_kernel<<<NB, 256, 0, s1>>>();
    hist_kernel<<<1024, 256, 0, s1>>>(edst);
    dinv_kernel<<<NB, 256, 0, s1>>>();

    dim3 g1grid(F_HID / BN, (N_NODES + BM - 1) / BM);
    gemm1_mma_kernel<<<g1grid, 256, DSMEM_BYTES>>>(x, W1, b1, W2);

    const int SCAN_BLOCKS = (N_NODES + 511) / 512;
    scan_block<<<SCAN_BLOCKS, 256, 0, s1>>>(pcount, prowstart, ppart, N_NODES);
    scan_block<<<1, 256, 0, s1>>>(ppart, ppscan, ppart, SCAN_BLOCKS);
    add_offsets<<<NB, 256, 0, s1>>>(prowstart, ppscan, N_NODES);
    scatter_kernel<<<1024, 256, 0, s1>>>(esrc, edst);
    cudaEventRecord(evJoin, s1);

    combine_kernel<<<(N_NODES * F_OUT / 4 + 255) / 256, 256>>>(b2);

    cudaStreamWaitEvent(0, evJoin, 0);

    float* score_out = nullptr;
    float* lsm_out = out;
    if (out_size >= N_NODES * F_OUT + N_NODES) {
        score_out = out + (size_t)N_NODES * F_OUT;
    } else if (out_size == N_NODES) {
        score_out = out;
        lsm_out = nullptr;
    }

    const int AMP_BLOCKS = (N_NODES * 32 + 255) / 256;
    // iter 0: fp16 h copy (g_hxb) -> fp16 A
    amp_kernel<false><<<AMP_BLOCKS, 256>>>((const uint2*)phxb, phxa, nullptr, nullptr);
    // iters 1..8: fp16 ping-pong
    __half* hb[2] = {phxa, phxb};
    for (int it = 1; it <= 8; it++) {
        __half* xin  = hb[(it - 1) & 1];
        __half* xout = hb[it & 1];
        amp_kernel<false><<<AMP_BLOCKS, 256>>>((const uint2*)xin, xout, nullptr, nullptr);
    }
    // iter 9: fp16 A -> fused log_softmax + score, straight to d_out
    amp_kernel<true><<<AMP_BLOCKS, 256>>>((const uint2*)phxa, nullptr, lsm_out, score_out);
}

// round 15
// speedup vs baseline: 1.0341x; 1.0341x over previous
#include <cuda_runtime.h>
#include <cuda_fp16.h>
#include <math.h>
#include <stdint.h>

#define N_NODES 100000
#define F_IN    500
#define F_HID   256
#define F_OUT   40
#define N_EDGES 1600000
#define K_ITERS 10

constexpr float LAMBDA_AMP = 0.5f;
constexpr float GAMMA_ = 1.0f / (2.0f * (1.0f - LAMBDA_AMP));   // 1.0
constexpr float COEF   = GAMMA_ * 2.0f * (1.0f - LAMBDA_AMP);   // 1.0
constexpr float LAM    = GAMMA_ * LAMBDA_AMP;                   // 0.5

// ---------------- device scratch (no allocations allowed) ----------------
__device__ __align__(16) float g_part_h[(size_t)2 * N_NODES * F_OUT];
__device__ __align__(16) float g_h [(size_t)N_NODES * F_OUT];
__device__ __align__(16) __half g_hxa[(size_t)N_NODES * F_OUT]; // fp16 ping
__device__ __align__(16) __half g_hxb[(size_t)N_NODES * F_OUT]; // fp16 pong (also fp16 h copy)
__device__ int    g_count[N_NODES];
__device__ int    g_rowstart[N_NODES];
__device__ int    g_cursor[N_NODES];
__device__ float  g_dinv[N_NODES];
__device__ __align__(16) float2 g_csr_sw[N_EDGES];   // {src_bits, weight}
__device__ int    g_part[512];
__device__ int    g_pscan[512];

// ---------------- setup kernels ----------------
__global__ void zero_kernel() {
    int i = blockIdx.x * blockDim.x + threadIdx.x;
    if (i < N_NODES) { g_count[i] = 0; g_cursor[i] = 0; }
}

__global__ void hist_kernel(const int* __restrict__ dst) {
    for (int e = blockIdx.x * blockDim.x + threadIdx.x; e < N_EDGES;
         e += gridDim.x * blockDim.x)
        atomicAdd(&g_count[dst[e]], 1);
}

__global__ void dinv_kernel() {
    int i = blockIdx.x * blockDim.x + threadIdx.x;
    if (i < N_NODES) {
        float deg = (float)(g_count[i] + 1);
        g_dinv[i] = rsqrtf(deg);
    }
}

__global__ void scan_block(const int* __restrict__ in, int* __restrict__ out,
                           int* __restrict__ partials, int n) {
    int t = threadIdx.x, lane = t & 31, w = t >> 5;
    int g = blockIdx.x * 512 + 2 * t;
    int v0 = (g     < n) ? in[g]     : 0;
    int v1 = (g + 1 < n) ? in[g + 1] : 0;
    int s = v0 + v1;
    int x = s;
#pragma unroll
    for (int o = 1; o < 32; o <<= 1) {
        int y = __shfl_up_sync(0xffffffffu, x, o);
        if (lane >= o) x += y;
    }
    __shared__ int wsum[8];
    if (lane == 31) wsum[w] = x;
    __syncthreads();
    if (w == 0) {
        int ws = (lane < 8) ? wsum[lane] : 0;
#pragma unroll
        for (int o = 1; o < 8; o <<= 1) {
            int y = __shfl_up_sync(0xffffffffu, ws, o);
            if (lane >= o) ws += y;
        }
        if (lane < 8) wsum[lane] = ws;
    }
    __syncthreads();
    int base = (w > 0) ? wsum[w - 1] : 0;
    int excl = base + x - s;
    if (g     < n) out[g]     = excl;
    if (g + 1 < n) out[g + 1] = excl + v0;
    if (t == 255) partials[blockIdx.x] = base + x;
}

__global__ void add_offsets(int* __restrict__ out, const int* __restrict__ pscan, int n) {
    int i = blockIdx.x * blockDim.x + threadIdx.x;
    if (i < n) out[i] += pscan[i >> 9];
}

__global__ void scatter_kernel(const int* __restrict__ src, const int* __restrict__ dst) {
    for (int e = blockIdx.x * blockDim.x + threadIdx.x; e < N_EDGES;
         e += gridDim.x * blockDim.x) {
        int d = dst[e], s = src[e];
        int pos = g_rowstart[d] + atomicAdd(&g_cursor[d], 1);
        g_csr_sw[pos] = make_float2(__int_as_float(s), g_dinv[s] * g_dinv[d]);
    }
}

// ---------------- fused MLP (tf32 mma.sync), big tiles + 3-stage cp.async ----
// A-fragments via ldmatrix.m8n8.x4.b16 (tf32 layout maps exactly)
#define BM 256
#define BN 128
#define BK 32
#define AS_STRIDE 36
#define BS_STRIDE 136
#define HT_STRIDE 136
#define W2_STRIDE 136
#define AS_W 9216
#define BS_W 4352
#define B_BASE 27648
#define DSMEM_BYTES (40704 * 4)

__device__ __forceinline__ uint32_t smem_u32(const void* p) {
    uint32_t a;
    asm("{ .reg .u64 t; cvta.to.shared.u64 t, %1; cvt.u32.u64 %0, t; }"
        : "=r"(a) : "l"(p));
    return a;
}
__device__ __forceinline__ void cp16(uint32_t dst, const void* src, int srcsz) {
    asm volatile("cp.async.ca.shared.global [%0], [%1], 16, %2;"
                 :: "r"(dst), "l"(src), "r"(srcsz) : "memory");
}
#define CP_COMMIT() asm volatile("cp.async.commit_group;" ::: "memory")
#define CP_WAIT2()  asm volatile("cp.async.wait_group 2;" ::: "memory")
#define CP_WAIT1()  asm volatile("cp.async.wait_group 1;" ::: "memory")
#define CP_WAIT0()  asm volatile("cp.async.wait_group 0;" ::: "memory")

__device__ __forceinline__ uint32_t f2tf32(float f) {
    uint32_t r;
    asm("cvt.rna.tf32.f32 %0, %1;" : "=r"(r) : "f"(f));
    return r;
}

__global__ __launch_bounds__(256, 1) void gemm1_mma_kernel(const float* __restrict__ A,
                                                           const float* __restrict__ B,
                                                           const float* __restrict__ bias,
                                                           const float* __restrict__ W2) {
    extern __shared__ __align__(16) uint32_t smem_u[];

    int bm = blockIdx.y * BM, bn = blockIdx.x * BN;
    int tid = threadIdx.x;
    int warpId = tid >> 5, lane = tid & 31;
    int warpM = warpId & 3;
    int warpN = warpId >> 2;
    int group = lane >> 2;
    int tig   = lane & 3;

    uint32_t sbase = smem_u32(smem_u);

    int lm_row  = warpM * 64 + (lane & 15);
    int lm_kcol = (lane & 16) ? 4 : 0;

    float acc[4][8][4] = {};

    auto issue_stage = [&](int it) {
        int buf = it % 3;
        int k0 = it * BK;
        uint32_t as_addr = sbase + (buf * AS_W) * 4;
        uint32_t bs_addr = sbase + (B_BASE + buf * BS_W) * 4;
#pragma unroll
        for (int i = 0; i < 8; i++) {
            int idx = tid + i * 256;
            int r = idx >> 3, q = idx & 7;
            int gm = bm + r, gk = k0 + q * 4;
            bool ok = (gm < N_NODES) && (gk < F_IN);
            int gmc = ok ? gm : 0, gkc = ok ? gk : 0;
            cp16(as_addr + (r * AS_STRIDE + q * 4) * 4,
                 A + (size_t)gmc * F_IN + gkc, ok ? 16 : 0);
        }
#pragma unroll
        for (int i = 0; i < 4; i++) {
            int idx = tid + i * 256;
            int kk = idx >> 5, c4 = idx & 31;
            int gk = k0 + kk;
            bool ok = (gk < F_IN);
            int gkc = ok ? gk : 0;
            cp16(bs_addr + (kk * BS_STRIDE + c4 * 4) * 4,
                 B + (size_t)gkc * F_HID + bn + c4 * 4, ok ? 16 : 0);
        }
        CP_COMMIT();
    };

    issue_stage(0);
    issue_stage(1);
    for (int it = 0; it < 16; it++) {
        int buf = it % 3;
        if (it <= 13) { issue_stage(it + 2); CP_WAIT2(); }
        else if (it == 14) { CP_WAIT1(); }
        else { CP_WAIT0(); }
        __syncthreads();

        const uint32_t* Bs = smem_u + B_BASE + buf * BS_W;
        uint32_t a_lm = sbase + (buf * AS_W) * 4
                      + (lm_row * AS_STRIDE + lm_kcol) * 4;
#pragma unroll
        for (int ks = 0; ks < BK / 8; ks++) {
            int kb = ks * 8;
            uint32_t af[4][4];
#pragma unroll
            for (int mi = 0; mi < 4; mi++) {
                uint32_t addr = a_lm + (mi * 16 * AS_STRIDE + kb) * 4;
                asm volatile(
                    "ldmatrix.sync.aligned.m8n8.x4.shared.b16 {%0,%1,%2,%3}, [%4];"
                    : "=r"(af[mi][0]), "=r"(af[mi][1]),
                      "=r"(af[mi][2]), "=r"(af[mi][3])
                    : "r"(addr));
            }
            uint32_t bf[8][2];
#pragma unroll
            for (int ni = 0; ni < 8; ni++) {
                int c0 = warpN * 64 + ni * 8 + group;
                bf[ni][0] = Bs[(kb + tig) * BS_STRIDE + c0];
                bf[ni][1] = Bs[(kb + tig + 4) * BS_STRIDE + c0];
            }
#pragma unroll
            for (int mi = 0; mi < 4; mi++)
#pragma unroll
                for (int ni = 0; ni < 8; ni++) {
                    asm volatile(
                        "mma.sync.aligned.m16n8k8.row.col.f32.tf32.tf32.f32 "
                        "{%0,%1,%2,%3}, {%4,%5,%6,%7}, {%8,%9}, {%0,%1,%2,%3};"
                        : "+f"(acc[mi][ni][0]), "+f"(acc[mi][ni][1]),
                          "+f"(acc[mi][ni][2]), "+f"(acc[mi][ni][3])
                        : "r"(af[mi][0]), "r"(af[mi][1]), "r"(af[mi][2]), "r"(af[mi][3]),
                          "r"(bf[ni][0]), "r"(bf[ni][1]));
                }
        }
        __syncthreads();
    }

    uint32_t* Ht  = smem_u;
    uint32_t* W2s = smem_u + 34816;

#pragma unroll
    for (int mi = 0; mi < 4; mi++) {
#pragma unroll
        for (int ni = 0; ni < 8; ni++) {
            int lc = warpN * 64 + ni * 8 + tig * 2;
            float bz0 = bias[bn + lc], bz1 = bias[bn + lc + 1];
            int r0 = warpM * 64 + mi * 16 + group;
            Ht[r0 * HT_STRIDE + lc]     = f2tf32(fmaxf(acc[mi][ni][0] + bz0, 0.f));
            Ht[r0 * HT_STRIDE + lc + 1] = f2tf32(fmaxf(acc[mi][ni][1] + bz1, 0.f));
            int r1 = r0 + 8;
            Ht[r1 * HT_STRIDE + lc]     = f2tf32(fmaxf(acc[mi][ni][2] + bz0, 0.f));
            Ht[r1 * HT_STRIDE + lc + 1] = f2tf32(fmaxf(acc[mi][ni][3] + bz1, 0.f));
        }
    }
    for (int idx = tid; idx < 40 * 128; idx += 256) {
        int n = idx >> 7, kk = idx & 127;
        W2s[n * W2_STRIDE + kk] = f2tf32(W2[(size_t)(bn + kk) * F_OUT + n]);
    }
    __syncthreads();

    float acc2[2][5][4] = {};
    int wrow = warpId * 32;
#pragma unroll
    for (int ks = 0; ks < 16; ks++) {
        int kb = ks * 8;
        uint32_t af[2][4];
#pragma unroll
        for (int mi = 0; mi < 2; mi++) {
            int r0 = wrow + mi * 16 + group;
            af[mi][0] = Ht[r0 * HT_STRIDE + kb + tig];
            af[mi][1] = Ht[(r0 + 8) * HT_STRIDE + kb + tig];
            af[mi][2] = Ht[r0 * HT_STRIDE + kb + tig + 4];
            af[mi][3] = Ht[(r0 + 8) * HT_STRIDE + kb + tig + 4];
        }
#pragma unroll
        for (int ni = 0; ni < 5; ni++) {
            uint32_t b0 = W2s[(ni * 8 + group) * W2_STRIDE + kb + tig];
            uint32_t b1 = W2s[(ni * 8 + group) * W2_STRIDE + kb + tig + 4];
#pragma unroll
            for (int mi = 0; mi < 2; mi++) {
                asm volatile(
                    "mma.sync.aligned.m16n8k8.row.col.f32.tf32.tf32.f32 "
                    "{%0,%1,%2,%3}, {%4,%5,%6,%7}, {%8,%9}, {%0,%1,%2,%3};"
                    : "+f"(acc2[mi][ni][0]), "+f"(acc2[mi][ni][1]),
                      "+f"(acc2[mi][ni][2]), "+f"(acc2[mi][ni][3])
                    : "r"(af[mi][0]), "r"(af[mi][1]), "r"(af[mi][2]), "r"(af[mi][3]),
                      "r"(b0), "r"(b1));
            }
        }
    }

    float* part = g_part_h + (size_t)blockIdx.x * N_NODES * F_OUT;
#pragma unroll
    for (int mi = 0; mi < 2; mi++) {
#pragma unroll
        for (int ni = 0; ni < 5; ni++) {
            int col = ni * 8 + tig * 2;
            int r0 = bm + wrow + mi * 16 + group;
            if (r0 < N_NODES)
                *(float2*)(part + (size_t)r0 * F_OUT + col) =
                    make_float2(acc2[mi][ni][0], acc2[mi][ni][1]);
            int r1 = r0 + 8;
            if (r1 < N_NODES)
                *(float2*)(part + (size_t)r1 * F_OUT + col) =
                    make_float2(acc2[mi][ni][2], acc2[mi][ni][3]);
        }
    }
}

// ---------------- fp16 pack/unpack ----------------
__device__ __forceinline__ float4 h4f4(uint2 u) {
    __half2 a = *(__half2*)&u.x, b = *(__half2*)&u.y;
    float2 fa = __half22float2(a), fb = __half22float2(b);
    return make_float4(fa.x, fa.y, fb.x, fb.y);
}
__device__ __forceinline__ uint2 f4h4(float4 v) {
    __half2 a = __floats2half2_rn(v.x, v.y);
    __half2 b = __floats2half2_rn(v.z, v.w);
    uint2 u;
    u.x = *(uint32_t*)&a;
    u.y = *(uint32_t*)&b;
    return u;
}

// ---------------- combine: h = b2 + sum of 2 partials (+ fp16 copy) --------
__global__ __launch_bounds__(256) void combine_kernel(const float* __restrict__ b2) {
    int idx = blockIdx.x * 256 + threadIdx.x;
    const int TOT = N_NODES * F_OUT / 4;
    if (idx >= TOT) return;
    const float4* p = (const float4*)g_part_h;
    const size_t STRIDE4 = (size_t)N_NODES * F_OUT / 4;
    float4 a = p[idx];
    float4 b = p[idx + STRIDE4];
    float4 bz = ((const float4*)b2)[idx % (F_OUT / 4)];
    float4 r;
    r.x = a.x + b.x + bz.x;
    r.y = a.y + b.y + bz.y;
    r.z = a.z + b.z + bz.z;
    r.w = a.w + b.w + bz.w;
    ((float4*)g_h)[idx] = r;
    ((uint2*)g_hxb)[idx] = f4h4(r);    // fp16 copy for iter-0 gathers
}

// ---------------- AMP: warp per node, 3 groups of 10 lanes ----------------
// occupancy-forced 6 CTAs/SM (r13-measured-good); FINAL fuses log_softmax+score
template<bool FINAL>
__global__ __launch_bounds__(256, 6) void amp_kernel(const uint2* __restrict__ xk2,
                                                     __half* __restrict__ xout_h,
                                                     float* __restrict__ lsm,
                                                     float* __restrict__ sout) {
    int node = (blockIdx.x * 256 + threadIdx.x) >> 5;
    int lane = threadIdx.x & 31;
    if (node >= N_NODES) return;
    int g = lane >= 30 ? 3 : (lane >= 20 ? 2 : (lane >= 10 ? 1 : 0));
    int sub = lane - g * 10;
    if (g == 3) sub = lane - 30;
    bool act = lane < 30;

    float4 xq = make_float4(0.f, 0.f, 0.f, 0.f);
    float4 accA = make_float4(0.f, 0.f, 0.f, 0.f);
    float4 accB = make_float4(0.f, 0.f, 0.f, 0.f);
    if (g == 0) {
        xq = h4f4(xk2[(size_t)node * 10 + sub]);
        float dv = g_dinv[node];
        float wself = dv * dv;
        accA.x = wself * xq.x; accA.y = wself * xq.y;
        accA.z = wself * xq.z; accA.w = wself * xq.w;
    }

    int beg = g_rowstart[node];
    int cnt = g_count[node];
    int base = 0;
    for (; base + 6 <= cnt; base += 6) {
        float2 swA = act ? g_csr_sw[beg + base + g]     : make_float2(0.f, 0.f);
        float2 swB = act ? g_csr_sw[beg + base + 3 + g] : make_float2(0.f, 0.f);
        int sA = act ? __float_as_int(swA.x) : 0;
        int sB = act ? __float_as_int(swB.x) : 0;
        float4 xA = h4f4(xk2[(size_t)sA * 10 + sub]);
        float4 xB = h4f4(xk2[(size_t)sB * 10 + sub]);
        accA.x += swA.y * xA.x; accA.y += swA.y * xA.y;
        accA.z += swA.y * xA.z; accA.w += swA.y * xA.w;
        accB.x += swB.y * xB.x; accB.y += swB.y * xB.y;
        accB.z += swB.y * xB.z; accB.w += swB.y * xB.w;
    }
    for (; base < cnt; base += 3) {
        int idx = base + g;
        bool v = act && (idx < cnt);
        float2 sw = v ? g_csr_sw[beg + idx] : make_float2(0.f, 0.f);
        int s = v ? __float_as_int(sw.x) : 0;
        float4 xs = h4f4(xk2[(size_t)s * 10 + sub]);
        accA.x += sw.y * xs.x; accA.y += sw.y * xs.y;
        accA.z += sw.y * xs.z; accA.w += sw.y * xs.w;
    }
    accA.x += accB.x; accA.y += accB.y; accA.z += accB.z; accA.w += accB.w;

    {
        float t1, t2;
        t1 = __shfl_down_sync(0xffffffffu, accA.x, 10);
        t2 = __shfl_down_sync(0xffffffffu, accA.x, 20);
        accA.x += t1 + t2;
        t1 = __shfl_down_sync(0xffffffffu, accA.y, 10);
        t2 = __shfl_down_sync(0xffffffffu, accA.y, 20);
        accA.y += t1 + t2;
        t1 = __shfl_down_sync(0xffffffffu, accA.z, 10);
        t2 = __shfl_down_sync(0xffffffffu, accA.z, 20);
        accA.z += t1 + t2;
        t1 = __shfl_down_sync(0xffffffffu, accA.w, 10);
        t2 = __shfl_down_sync(0xffffffffu, accA.w, 20);
        accA.w += t1 + t2;
    }

    float4 hq = make_float4(0.f, 0.f, 0.f, 0.f);
    float4 d = make_float4(0.f, 0.f, 0.f, 0.f);
    float ss = 0.f;
    if (g == 0) {
        hq = ((const float4*)g_h)[(size_t)node * 10 + sub];
        float4 y;
        y.x = xq.x - COEF * (xq.x - accA.x);
        y.y = xq.y - COEF * (xq.y - accA.y);
        y.z = xq.z - COEF * (xq.z - accA.z);
        y.w = xq.w - COEF * (xq.w - accA.w);
        d.x = y.x - hq.x; d.y = y.y - hq.y; d.z = y.z - hq.z; d.w = y.w - hq.w;
        ss = d.x * d.x + d.y * d.y + d.z * d.z + d.w * d.w;
    }
#pragma unroll
    for (int o = 16; o > 0; o >>= 1) ss += __shfl_xor_sync(0xffffffffu, ss, o);
    float rn = sqrtf(ss);
    float score = (rn > 0.f) ? fmaxf(rn - LAM, 0.f) / rn : 0.f;

    float4 r = make_float4(0.f, 0.f, 0.f, 0.f);
    if (g == 0) {
        r.x = hq.x + score * d.x; r.y = hq.y + score * d.y;
        r.z = hq.z + score * d.z; r.w = hq.w + score * d.w;
    }

    if (!FINAL) {
        if (g == 0)
            ((uint2*)xout_h)[(size_t)node * 10 + sub] = f4h4(r);
    } else {
        // fused log_softmax over the 40 values held by lanes 0-9
        float m_l = -INFINITY, e_l = 0.f;
        if (g == 0)
            m_l = fmaxf(fmaxf(r.x, r.y), fmaxf(r.z, r.w));
#pragma unroll
        for (int o = 16; o > 0; o >>= 1)
            m_l = fmaxf(m_l, __shfl_xor_sync(0xffffffffu, m_l, o));
        if (g == 0)
            e_l = expf(r.x - m_l) + expf(r.y - m_l) + expf(r.z - m_l) + expf(r.w - m_l);
#pragma unroll
        for (int o = 16; o > 0; o >>= 1)
            e_l += __shfl_xor_sync(0xffffffffu, e_l, o);
        float lse = m_l + logf(e_l);
        if (g == 0 && lsm) {
            float4 o4 = make_float4(r.x - lse, r.y - lse, r.z - lse, r.w - lse);
            ((float4*)lsm)[(size_t)node * 10 + sub] = o4;
        }
        if (lane == 0 && sout) sout[node] = score;
    }
}

// ---------------- launch ----------------
extern "C" void kernel_launch(void* const* d_in, const int* in_sizes, int n_in,
                              void* d_out, int out_size) {
    const float* x   = (const float*)d_in[0];
    const float* W1  = (const float*)d_in[1];
    const float* b1  = (const float*)d_in[2];
    const float* W2  = (const float*)d_in[3];
    const float* b2  = (const float*)d_in[4];
    const int* esrc  = (const int*)d_in[5];
    const int* edst  = (const int*)d_in[6];
    float* out = (float*)d_out;

    __half *phxa, *phxb;
    int *pcount, *prowstart, *ppart, *ppscan;
    cudaGetSymbolAddress((void**)&phxa, g_hxa);
    cudaGetSymbolAddress((void**)&phxb, g_hxb);
    cudaGetSymbolAddress((void**)&pcount,    g_count);
    cudaGetSymbolAddress((void**)&prowstart, g_rowstart);
    cudaGetSymbolAddress((void**)&ppart,     g_part);
    cudaGetSymbolAddress((void**)&ppscan,    g_pscan);

    static cudaStream_t s1 = nullptr;
    static cudaEvent_t evFork = nullptr, evJoin = nullptr;
    if (!s1) {
        cudaStreamCreateWithFlags(&s1, cudaStreamNonBlocking);
        cudaEventCreateWithFlags(&evFork, cudaEventDisableTiming);
        cudaEventCreateWithFlags(&evJoin, cudaEventDisableTiming);
        cudaFuncSetAttribute(gemm1_mma_kernel,
                             cudaFuncAttributeMaxDynamicSharedMemorySize, DSMEM_BYTES);
    }

    const int NB = (N_NODES + 255) / 256;

    // fork: setup chain on s1, MLP on main stream
    cudaEventRecord(evFork, 0);
    cudaStreamWaitEvent(s1, evFork, 0);

    zero_kernel<<<NB, 256, 0, s1>>>();
    hist_kernel<<<1024, 256, 0, s1>>>(edst);
    dinv_kernel<<<NB, 256, 0, s1>>>();

    dim3 g1grid(F_HID / BN, (N_NODES + BM - 1) / BM);
    gemm1_mma_kernel<<<g1grid, 256, DSMEM_BYTES>>>(x, W1, b1, W2);

    const int SCAN_BLOCKS = (N_NODES + 511) / 512;
    scan_block<<<SCAN_BLOCKS, 256, 0, s1>>>(pcount, prowstart, ppart, N_NODES);
    scan_block<<<1, 256, 0, s1>>>(ppart, ppscan, ppart, SCAN_BLOCKS);
    add_offsets<<<NB, 256, 0, s1>>>(prowstart, ppscan, N_NODES);
    scatter_kernel<<<1024, 256, 0, s1>>>(esrc, edst);
    cudaEventRecord(evJoin, s1);

    combine_kernel<<<(N_NODES * F_OUT / 4 + 255) / 256, 256>>>(b2);

    cudaStreamWaitEvent(0, evJoin, 0);

    float* score_out = nullptr;
    float* lsm_out = out;
    if (out_size >= N_NODES * F_OUT + N_NODES) {
        score_out = out + (size_t)N_NODES * F_OUT;
    } else if (out_size == N_NODES) {
        score_out = out;
        lsm_out = nullptr;
    }

    const int AMP_BLOCKS = (N_NODES * 32 + 255) / 256;
    // iter 0: fp16 h copy (g_hxb) -> fp16 A
    amp_kernel<false><<<AMP_BLOCKS, 256>>>((const uint2*)phxb, phxa, nullptr, nullptr);
    // iters 1..8: fp16 ping-pong
    __half* hb[2] = {phxa, phxb};
    for (int it = 1; it <= 8; it++) {
        __half* xin  = hb[(it - 1) & 1];
        __half* xout = hb[it & 1];
        amp_kernel<false><<<AMP_BLOCKS, 256>>>((const uint2*)xin, xout, nullptr, nullptr);
    }
    // iter 9: fp16 A -> fused log_softmax + score, straight to d_out
    amp_kernel<true><<<AMP_BLOCKS, 256>>>((const uint2*)phxa, nullptr, lsm_out, score_out);
}